// round 17
// baseline (speedup 1.0000x reference)
#include <cuda_runtime.h>
#include <math.h>
#include <stdint.h>

#define EMBED 384
#define NHEADS 6
#define HS 64
#define BATCH 4
#define TT 2048
#define MTOK (BATCH * TT)   // 8192
#define ATTN_SCALE 0.125f   // 64^-0.5

// ---- scratch (no cudaMalloc allowed) ----
__device__ float g_Q[(size_t)BATCH * NHEADS * TT * HS];   // [B,H,T,64]
__device__ float g_cat[(size_t)MTOK * EMBED];
__device__ float g_t1[(size_t)MTOK * EMBED];
__device__ float g_x1[(size_t)MTOK * EMBED];
__device__ float g_t2[(size_t)MTOK * EMBED];

// ---- packed f32x2 helpers (SASS FFMA2; PTX fma.rn.f32x2, sm_100+) ----
__device__ __forceinline__ unsigned long long pk2dup(float x) {
  unsigned long long r;
  asm("mov.b64 %0, {%1, %1};" : "=l"(r) : "f"(x));
  return r;
}
__device__ __forceinline__ unsigned long long fma2(unsigned long long a,
                                                   unsigned long long b,
                                                   unsigned long long c) {
  unsigned long long d;
  asm("fma.rn.f32x2 %0, %1, %2, %3;" : "=l"(d) : "l"(a), "l"(b), "l"(c));
  return d;
}
__device__ __forceinline__ unsigned long long mul2(unsigned long long a,
                                                   unsigned long long b) {
  unsigned long long d;
  asm("mul.rn.f32x2 %0, %1, %2;" : "=l"(d) : "l"(a), "l"(b));
  return d;
}
__device__ __forceinline__ void unpk2(unsigned long long v, float& lo, float& hi) {
  asm("mov.b64 {%0, %1}, %2;" : "=f"(lo), "=f"(hi) : "l"(v));
}

// ============================================================
// Tiled SGEMM: C[M,384] = A[M,384] @ W[384,384]^T (+bias)
// 128x64 CTA tile, 256 threads, 8 rows x 2 col-pairs (f32x2) per thread.
// W tile stored transposed (BsT[k][n]) so N col-pairs are contiguous.
// MODE 0: C = acc + bias
// MODE 1: C = relu(acc + bias)
// MODE 2: scatter acc into g_Q layout [B,H,T,64] (no bias)
// ============================================================
template <int MODE>
__global__ __launch_bounds__(256) void gemm384_kernel(
    const float* __restrict__ A, const float* __restrict__ W,
    const float* __restrict__ bias, float* __restrict__ C) {
  __shared__ float As[128][36];
  __shared__ float BsT[32][68];   // [k][n], n contiguous

  const int m0 = blockIdx.x * 128;
  const int n0 = blockIdx.y * 64;
  const int tid = threadIdx.x;
  const int tx = tid & 15;      // N: cols tx*4 .. tx*4+3 (2 pairs)
  const int ty = tid >> 4;      // M: rows ty*8 + i

  unsigned long long acc[8][2];
#pragma unroll
  for (int i = 0; i < 8; i++) { acc[i][0] = 0ull; acc[i][1] = 0ull; }

  for (int k0 = 0; k0 < EMBED; k0 += 32) {
    // A tile: 128x32 = 1024 float4, 4/thread
#pragma unroll
    for (int q = 0; q < 4; q++) {
      int idx = tid + q * 256;
      int r = idx >> 3;                 // 0..127
      int c4 = (idx & 7) << 2;          // 0..28
      *(float4*)&As[r][c4] =
          *(const float4*)&A[(size_t)(m0 + r) * EMBED + k0 + c4];
    }
    // W tile transposed: 64 n-rows x 32 k = 512 float4, 2/thread
#pragma unroll
    for (int q = 0; q < 2; q++) {
      int idx = tid + q * 256;
      int n = idx >> 3;                 // 0..63
      int kq = (idx & 7) << 2;          // k quad
      float4 w = *(const float4*)&W[(size_t)(n0 + n) * EMBED + k0 + kq];
      BsT[kq + 0][n] = w.x;
      BsT[kq + 1][n] = w.y;
      BsT[kq + 2][n] = w.z;
      BsT[kq + 3][n] = w.w;
    }
    __syncthreads();

#pragma unroll
    for (int k4 = 0; k4 < 8; k4++) {
      ulonglong2 bp[4];
#pragma unroll
      for (int kk = 0; kk < 4; kk++)
        bp[kk] = *(ulonglong2*)&BsT[k4 * 4 + kk][tx * 4];
#pragma unroll
      for (int i = 0; i < 8; i++) {
        float4 av = *(float4*)&As[ty * 8 + i][k4 * 4];
        const float* ap = (const float*)&av;
#pragma unroll
        for (int kk = 0; kk < 4; kk++) {
          unsigned long long ad = pk2dup(ap[kk]);
          acc[i][0] = fma2(ad, bp[kk].x, acc[i][0]);
          acc[i][1] = fma2(ad, bp[kk].y, acc[i][1]);
        }
      }
    }
    __syncthreads();
  }

  float4 bb;
  if (MODE != 2) bb = *(const float4*)&bias[n0 + tx * 4];
#pragma unroll
  for (int i = 0; i < 8; i++) {
    int m = m0 + ty * 8 + i;
    float c0, c1, c2, c3;
    unpk2(acc[i][0], c0, c1);
    unpk2(acc[i][1], c2, c3);
    if (MODE == 0) {
      float4 ov = {c0 + bb.x, c1 + bb.y, c2 + bb.z, c3 + bb.w};
      *(float4*)&C[(size_t)m * EMBED + n0 + tx * 4] = ov;
    } else if (MODE == 1) {
      float4 ov = {fmaxf(c0 + bb.x, 0.0f), fmaxf(c1 + bb.y, 0.0f),
                   fmaxf(c2 + bb.z, 0.0f), fmaxf(c3 + bb.w, 0.0f)};
      *(float4*)&C[(size_t)m * EMBED + n0 + tx * 4] = ov;
    } else {
      int b = m >> 11;
      int t = m & 2047;
      int h = n0 >> 6;            // whole tile inside one head
      float4 ov = {c0, c1, c2, c3};
      *(float4*)&C[(((size_t)(b * NHEADS + h)) * TT + t) * HS + tx * 4] = ov;
    }
  }
}

// ============================================================
// Flash attention (fp32 SIMT, f32x2 packed), q = k = v.
// 64 q-rows x 128 keys/chunk, 256 threads (16x16).
// S phase: keys tx*8..tx*8+7 per thread, packed pairs from KsT[d][key].
// PV phase: o cols tx*4..+3 (2 pairs), packed V pairs from Ks[key][d].
// KsT aliases Ps (disjoint lifetimes).
// Masking matches reference exactly.
// ============================================================
#define KC 128
#define QS_F (64 * 64)
#define KS_F (KC * 68)
#define UN_F (64 * 132)   // max(KsT 64x132, Ps 64x132)
#define ATTN_SMEM_BYTES ((QS_F + KS_F + UN_F) * 4)

__global__ __launch_bounds__(256, 2) void attn_kernel(
    const float* __restrict__ Q, float* __restrict__ cat) {
  extern __shared__ float sm[];
  float* Qs = sm;                    // [64][64]
  float* Ks = sm + QS_F;             // [128][68]
  float* KsT = sm + QS_F + KS_F;     // [64][132]  (aliases Ps)
  float* Ps = KsT;                   // [64][132]

  const int bh = blockIdx.y;
  const int qi = gridDim.x - 1 - blockIdx.x;  // big blocks first
  const float* Qb = Q + (size_t)bh * TT * HS;

  const int tid = threadIdx.x;
  const int tx = tid & 15;
  const int ty = tid >> 4;

  // load Q tile (64x64)
#pragma unroll
  for (int q = 0; q < 4; q++) {
    int idx = tid + q * 256;
    int r = idx >> 4;
    int c4 = (idx & 15) << 2;
    *(float4*)&Qs[r * 64 + c4] =
        *(const float4*)&Qb[(size_t)(qi * 64 + r) * HS + c4];
  }

  unsigned long long o2[4][2];
  float mi[4], li[4];
#pragma unroll
  for (int i = 0; i < 4; i++) {
    mi[i] = -INFINITY;
    li[i] = 0.0f;
    o2[i][0] = 0ull;
    o2[i][1] = 0ull;
  }

  const int nc = (qi >> 1) + 1;

  for (int kt = 0; kt < nc; kt++) {
    __syncthreads();  // prior PV readers done before Ks/KsT overwrite
    // load K chunk into Ks [key][d] and KsT [d][key]
#pragma unroll
    for (int q = 0; q < 8; q++) {
      int idx = tid + q * 256;
      int r = idx >> 4;                 // key 0..127
      int c4 = (idx & 15) << 2;         // d quad
      float4 v = *(const float4*)&Qb[(size_t)(kt * KC + r) * HS + c4];
      *(float4*)&Ks[r * 68 + c4] = v;
      // KsT holds d rows (64) x key cols (128)
      KsT[(c4 + 0) * 132 + r] = v.x;
      KsT[(c4 + 1) * 132 + r] = v.y;
      KsT[(c4 + 2) * 132 + r] = v.z;
      KsT[(c4 + 3) * 132 + r] = v.w;
    }
    __syncthreads();

    // ---- S = Q * K^T, packed over key pairs ----
    unsigned long long s2[4][4];
#pragma unroll
    for (int i = 0; i < 4; i++)
#pragma unroll
      for (int p = 0; p < 4; p++) s2[i][p] = 0ull;

#pragma unroll
    for (int d4 = 0; d4 < 16; d4++) {
      float4 av[4];
#pragma unroll
      for (int i = 0; i < 4; i++)
        av[i] = *(float4*)&Qs[(ty * 4 + i) * 64 + d4 * 4];
#pragma unroll
      for (int dd = 0; dd < 4; dd++) {
        int d = d4 * 4 + dd;
        ulonglong2 bA = *(ulonglong2*)&KsT[d * 132 + tx * 8];
        ulonglong2 bB = *(ulonglong2*)&KsT[d * 132 + tx * 8 + 4];
#pragma unroll
        for (int i = 0; i < 4; i++) {
          unsigned long long ad = pk2dup(((const float*)&av[i])[dd]);
          s2[i][0] = fma2(ad, bA.x, s2[i][0]);
          s2[i][1] = fma2(ad, bA.y, s2[i][1]);
          s2[i][2] = fma2(ad, bB.x, s2[i][2]);
          s2[i][3] = fma2(ad, bB.y, s2[i][3]);
        }
      }
    }

    // unpack, scale + mask (exact reference quirk), softmax
    float s[4][8];
#pragma unroll
    for (int i = 0; i < 4; i++)
#pragma unroll
      for (int p = 0; p < 4; p++)
        unpk2(s2[i][p], s[i][2 * p], s[i][2 * p + 1]);

#pragma unroll
    for (int i = 0; i < 4; i++) {
      int r = qi * 64 + ty * 4 + i;
#pragma unroll
      for (int j = 0; j < 8; j++) {
        int c = kt * KC + tx * 8 + j;
        float v = s[i][j] * ATTN_SCALE;
        if (c > r || v == 0.0f) v = -INFINITY;
        s[i][j] = v;
      }
    }

#pragma unroll
    for (int i = 0; i < 4; i++) {
      float rm = s[i][0];
#pragma unroll
      for (int j = 1; j < 8; j++) rm = fmaxf(rm, s[i][j]);
#pragma unroll
      for (int off = 8; off > 0; off >>= 1)
        rm = fmaxf(rm, __shfl_xor_sync(0xffffffffu, rm, off));
      float nm = fmaxf(mi[i], rm);
      float alpha = (mi[i] == -INFINITY) ? 0.0f : __expf(mi[i] - nm);
      float psum = 0.0f;
#pragma unroll
      for (int j = 0; j < 8; j++) {
        float p = __expf(s[i][j] - nm);
        s[i][j] = p;
        psum += p;
      }
#pragma unroll
      for (int off = 8; off > 0; off >>= 1)
        psum += __shfl_xor_sync(0xffffffffu, psum, off);
      li[i] = li[i] * alpha + psum;
      mi[i] = nm;
      unsigned long long a2 = pk2dup(alpha);
      o2[i][0] = mul2(o2[i][0], a2);
      o2[i][1] = mul2(o2[i][1], a2);
    }

    __syncthreads();  // all KsT reads done before Ps (alias) writes

    // stage P
#pragma unroll
    for (int i = 0; i < 4; i++)
#pragma unroll
      for (int p = 0; p < 4; p++) {
        float2 pv = make_float2(s[i][2 * p], s[i][2 * p + 1]);
        *(float2*)&Ps[(ty * 4 + i) * 132 + tx * 8 + 2 * p] = pv;
      }
    __syncthreads();

    // ---- O += P * V (V == Ks), packed over d pairs ----
#pragma unroll
    for (int k4 = 0; k4 < KC / 4; k4++) {
      float4 p4[4];
#pragma unroll
      for (int i = 0; i < 4; i++)
        p4[i] = *(float4*)&Ps[(ty * 4 + i) * 132 + k4 * 4];
#pragma unroll
      for (int kk = 0; kk < 4; kk++) {
        int k = k4 * 4 + kk;
        ulonglong2 v2 = *(ulonglong2*)&Ks[k * 68 + tx * 4];
#pragma unroll
        for (int i = 0; i < 4; i++) {
          unsigned long long pd = pk2dup(((const float*)&p4[i])[kk]);
          o2[i][0] = fma2(pd, v2.x, o2[i][0]);
          o2[i][1] = fma2(pd, v2.y, o2[i][1]);
        }
      }
    }
  }

  // ---- epilogue: normalize and write concat layout [B,T,384] ----
  const int b = bh / NHEADS;
  const int h = bh % NHEADS;
#pragma unroll
  for (int i = 0; i < 4; i++) {
    float inv = 1.0f / li[i];
    int t = qi * 64 + ty * 4 + i;
    size_t base = ((size_t)(b * TT + t)) * EMBED + h * HS;
    float c0, c1, c2, c3;
    unpk2(o2[i][0], c0, c1);
    unpk2(o2[i][1], c2, c3);
    float4 ov = {c0 * inv, c1 * inv, c2 * inv, c3 * inv};
    *(float4*)&cat[base + tx * 4] = ov;
  }
}

// ============================================================
// out = LayerNorm(a + res) * g + be   (one block per token row)
// ============================================================
__global__ __launch_bounds__(128) void add_ln_kernel(
    const float* __restrict__ a, const float* __restrict__ res,
    const float* __restrict__ g, const float* __restrict__ be,
    float* __restrict__ out) {
  __shared__ float red[8];
  const int row = blockIdx.x;
  const int tid = threadIdx.x;
  const size_t base = (size_t)row * EMBED;

  float v[3];
#pragma unroll
  for (int q = 0; q < 3; q++) {
    int c = tid + q * 128;
    v[q] = a[base + c] + res[base + c];
  }

  float s = v[0] + v[1] + v[2];
#pragma unroll
  for (int off = 16; off > 0; off >>= 1)
    s += __shfl_xor_sync(0xffffffffu, s, off);
  if ((tid & 31) == 0) red[tid >> 5] = s;
  __syncthreads();
  float mu = (red[0] + red[1] + red[2] + red[3]) * (1.0f / EMBED);

  float d0 = v[0] - mu, d1 = v[1] - mu, d2 = v[2] - mu;
  float sq = d0 * d0 + d1 * d1 + d2 * d2;
#pragma unroll
  for (int off = 16; off > 0; off >>= 1)
    sq += __shfl_xor_sync(0xffffffffu, sq, off);
  if ((tid & 31) == 0) red[4 + (tid >> 5)] = sq;
  __syncthreads();
  float var = (red[4] + red[5] + red[6] + red[7]) * (1.0f / EMBED);
  float inv = rsqrtf(var + 1e-5f);

  out[base + tid]       = d0 * inv * g[tid]       + be[tid];
  out[base + tid + 128] = d1 * inv * g[tid + 128] + be[tid + 128];
  out[base + tid + 256] = d2 * inv * g[tid + 256] + be[tid + 256];
}

// ============================================================
// launch
// ============================================================
extern "C" void kernel_launch(void* const* d_in, const int* in_sizes, int n_in,
                              void* d_out, int out_size) {
  const float* x   = (const float*)d_in[0];
  const float* Wq  = (const float*)d_in[1];
  const float* Wo  = (const float*)d_in[2];
  const float* bo  = (const float*)d_in[3];
  const float* W1  = (const float*)d_in[4];
  const float* b1  = (const float*)d_in[5];
  const float* W2  = (const float*)d_in[6];
  const float* b2  = (const float*)d_in[7];
  const float* g1  = (const float*)d_in[8];
  const float* be1 = (const float*)d_in[9];
  const float* g2  = (const float*)d_in[10];
  const float* be2 = (const float*)d_in[11];
  float* out = (float*)d_out;

  float *pQ, *pcat, *pt1, *px1, *pt2;
  cudaGetSymbolAddress((void**)&pQ, g_Q);
  cudaGetSymbolAddress((void**)&pcat, g_cat);
  cudaGetSymbolAddress((void**)&pt1, g_t1);
  cudaGetSymbolAddress((void**)&px1, g_x1);
  cudaGetSymbolAddress((void**)&pt2, g_t2);

  cudaFuncSetAttribute(attn_kernel,
                       cudaFuncAttributeMaxDynamicSharedMemorySize,
                       ATTN_SMEM_BYTES);

  dim3 gemm_grid(MTOK / 128, EMBED / 64);

  // 1. q = x @ Wq^T, scattered to [B,H,T,64]
  gemm384_kernel<2><<<gemm_grid, 256>>>(x, Wq, nullptr, pQ);

  // 2. causal self-attention (q=k=v), output in concat layout
  attn_kernel<<<dim3(TT / 64, BATCH * NHEADS), 256, ATTN_SMEM_BYTES>>>(pQ, pcat);

  // 3. sa = cat @ Wo^T + bo
  gemm384_kernel<0><<<gemm_grid, 256>>>(pcat, Wo, bo, pt1);

  // 4. x1 = LN(x + sa)
  add_ln_kernel<<<MTOK, 128>>>(pt1, x, g1, be1, px1);

  // 5. h = relu(x1 @ W1^T + b1)
  gemm384_kernel<1><<<gemm_grid, 256>>>(px1, W1, b1, pt2);

  // 6. ff = h @ W2^T + b2
  gemm384_kernel<0><<<gemm_grid, 256>>>(pt2, W2, b2, pt1);

  // 7. out = LN(x1 + ff)
  add_ln_kernel<<<MTOK, 128>>>(pt1, px1, g2, be2, out);
}